// round 1
// baseline (speedup 1.0000x reference)
#include <cuda_runtime.h>
#include <cstdint>

// Encoder_12240656794040
// features: [100000, 128] f32
// weight:   [4096, 256, 128] f32   (streamed once -> HBM bound)
// nodes:    [4096] i32
// neigh_idx:[4096, 10] i32
// out:      [4096, 128] f32
//
// out[b,e] = relu( sum_i combined[b,i] * weight[b,i,e] )
// combined = concat(features[nodes[b]], mean_j features[neigh_idx[b,j]])

#define FEAT 128
#define TWOF 256
#define EMB  128
#define NS   10

__global__ __launch_bounds__(128, 8)
void encoder_kernel(const float* __restrict__ features,
                    const float* __restrict__ weight,
                    const int*   __restrict__ nodes,
                    const int*   __restrict__ neigh,
                    float*       __restrict__ out)
{
    const int b    = blockIdx.x;
    const int t    = threadIdx.x;   // 0..127
    const int warp = t >> 5;
    const int lane = t & 31;

    __shared__ float comb[TWOF];
    __shared__ float4 part[4][32];

    // ---- Phase 1: build combined vector [256] in smem ----
    // self features
    {
        const int sn = nodes[b];
        comb[t] = __ldg(&features[(size_t)sn * FEAT + t]);
    }
    // neighbor mean
    {
        float acc = 0.f;
        const int* ni = neigh + (size_t)b * NS;
        #pragma unroll
        for (int j = 0; j < NS; ++j) {
            const int n = ni[j];
            acc += __ldg(&features[(size_t)n * FEAT + t]);
        }
        comb[FEAT + t] = acc * (1.0f / NS);
    }
    __syncthreads();

    // ---- Phase 2: per-row GEMV, weight streamed coalesced ----
    // Each warp handles i = warp, warp+4, ..., lanes cover all 128 e via float4.
    const float4* __restrict__ W =
        reinterpret_cast<const float4*>(weight + (size_t)b * TWOF * EMB);

    float4 a = make_float4(0.f, 0.f, 0.f, 0.f);
    #pragma unroll 8
    for (int i = warp; i < TWOF; i += 4) {
        const float  c = comb[i];
        const float4 w = __ldg(&W[i * (EMB / 4) + lane]);
        a.x = fmaf(c, w.x, a.x);
        a.y = fmaf(c, w.y, a.y);
        a.z = fmaf(c, w.z, a.z);
        a.w = fmaf(c, w.w, a.w);
    }
    part[warp][lane] = a;
    __syncthreads();

    if (warp == 0) {
        float4 s  = part[0][lane];
        float4 p1 = part[1][lane];
        float4 p2 = part[2][lane];
        float4 p3 = part[3][lane];
        s.x += p1.x + p2.x + p3.x;
        s.y += p1.y + p2.y + p3.y;
        s.z += p1.z + p2.z + p3.z;
        s.w += p1.w + p2.w + p3.w;
        s.x = fmaxf(s.x, 0.f);
        s.y = fmaxf(s.y, 0.f);
        s.z = fmaxf(s.z, 0.f);
        s.w = fmaxf(s.w, 0.f);
        reinterpret_cast<float4*>(out)[(size_t)b * (EMB / 4) + lane] = s;
    }
}

extern "C" void kernel_launch(void* const* d_in, const int* in_sizes, int n_in,
                              void* d_out, int out_size)
{
    const float* features = (const float*)d_in[0];
    const float* weight   = (const float*)d_in[1];
    const int*   nodes    = (const int*)d_in[2];
    const int*   neigh    = (const int*)d_in[3];
    float*       out      = (float*)d_out;

    const int batch = in_sizes[2];  // 4096 nodes
    encoder_kernel<<<batch, 128>>>(features, weight, nodes, neigh, out);
}

// round 3
// speedup vs baseline: 1.0074x; 1.0074x over previous
#include <cuda_runtime.h>
#include <cstdint>

// Encoder_12240656794040  — GraphSAGE encoder, HBM-streaming bound on weight.
// features: [100000, 128] f32  (51.2 MB -> keep resident in L2 across replays)
// weight:   [4096, 256, 128] f32 (536 MB, read once -> stream with evict-first)
// nodes:    [4096] i32
// neigh_idx:[4096, 10] i32
// out:      [4096, 128] f32

#define FEAT 128
#define TWOF 256
#define EMB  128
#define NS   10
#define GRID_PERSIST 1184   // 148 SMs * 8 CTAs

__global__ __launch_bounds__(128, 8)
void encoder_kernel(const float* __restrict__ features,
                    const float* __restrict__ weight,
                    const int*   __restrict__ nodes,
                    const int*   __restrict__ neigh,
                    float*       __restrict__ out,
                    int batch)
{
    const int t    = threadIdx.x;   // 0..127
    const int warp = t >> 5;
    const int lane = t & 31;

    __shared__ float comb[TWOF];
    __shared__ float4 part[4][32];

    for (int b = blockIdx.x; b < batch; b += gridDim.x) {
        // ---- Phase 1: build combined vector [256] in smem ----
        {
            const int sn = __ldg(&nodes[b]);
            comb[t] = __ldg(&features[(size_t)sn * FEAT + t]);

            float acc = 0.f;
            const int* ni = neigh + (size_t)b * NS;
            #pragma unroll
            for (int j = 0; j < NS; ++j) {
                const int n = __ldg(&ni[j]);
                acc += __ldg(&features[(size_t)n * FEAT + t]);
            }
            comb[FEAT + t] = acc * (1.0f / NS);
        }
        __syncthreads();

        // ---- Phase 2: per-row GEMV; weight streamed evict-first ----
        const float4* __restrict__ W =
            reinterpret_cast<const float4*>(weight + (size_t)b * TWOF * EMB);

        float4 a = make_float4(0.f, 0.f, 0.f, 0.f);
        #pragma unroll 8
        for (int i = warp; i < TWOF; i += 4) {
            const float  c = comb[i];
            const float4 w = __ldcs(&W[i * (EMB / 4) + lane]);
            a.x = fmaf(c, w.x, a.x);
            a.y = fmaf(c, w.y, a.y);
            a.z = fmaf(c, w.z, a.z);
            a.w = fmaf(c, w.w, a.w);
        }
        part[warp][lane] = a;
        __syncthreads();

        if (warp == 0) {
            float4 s  = part[0][lane];
            float4 p1 = part[1][lane];
            float4 p2 = part[2][lane];
            float4 p3 = part[3][lane];
            s.x += p1.x + p2.x + p3.x;
            s.y += p1.y + p2.y + p3.y;
            s.z += p1.z + p2.z + p3.z;
            s.w += p1.w + p2.w + p3.w;
            s.x = fmaxf(s.x, 0.f);
            s.y = fmaxf(s.y, 0.f);
            s.z = fmaxf(s.z, 0.f);
            s.w = fmaxf(s.w, 0.f);
            __stcs(&reinterpret_cast<float4*>(out)[(size_t)b * (EMB / 4) + lane], s);
        }
        // next-iteration __syncthreads (phase-1 boundary) orders the
        // warp-0 'part' reads against the next gemv's 'part' writes.
    }
}

extern "C" void kernel_launch(void* const* d_in, const int* in_sizes, int n_in,
                              void* d_out, int out_size)
{
    const float* features = (const float*)d_in[0];
    const float* weight   = (const float*)d_in[1];
    const int*   nodes    = (const int*)d_in[2];
    const int*   neigh    = (const int*)d_in[3];
    float*       out      = (float*)d_out;

    const int batch = in_sizes[2];  // 4096 nodes
    const int grid  = batch < GRID_PERSIST ? batch : GRID_PERSIST;
    encoder_kernel<<<grid, 128>>>(features, weight, nodes, neigh, out, batch);
}